// round 14
// baseline (speedup 1.0000x reference)
#include <cuda_runtime.h>
#include <cuda_fp16.h>
#include <cstdint>

#define NB   4
#define NSEQ 4096
#define CDIM 512
#define DDIM 64

// fp16 scratch (allocation-free rule: __device__ globals)
__device__ __half g_qh[NB * NSEQ * DDIM];   // Q = (x @ g) * log2e
__device__ __half g_kh[NB * NSEQ * DDIM];   // K = input_h @ f
__device__ __half g_hh[NB * NSEQ * CDIM];   // input_h fp16

#define SWZ(x) ((x) ^ (((x) >> 3) & 0x70))
#define ONES_H2 0x3C003C00u

// ---------------------------------------------------------------------------
__device__ __forceinline__ uint32_t smem_u32(const void* p) {
    uint32_t a;
    asm("{ .reg .u64 t; cvta.to.shared.u64 t, %1; cvt.u32.u64 %0, t; }" : "=r"(a) : "l"(p));
    return a;
}
__device__ __forceinline__ void cp16(uint32_t s, const void* g) {
    asm volatile("cp.async.cg.shared.global [%0], [%1], 16;" :: "r"(s), "l"(g));
}
#define CP_COMMIT() asm volatile("cp.async.commit_group;" ::: "memory")
#define CP_WAIT0()  asm volatile("cp.async.wait_group 0;" ::: "memory")

__device__ __forceinline__ void ldsm4(uint32_t* r, uint32_t a) {
    asm volatile("ldmatrix.sync.aligned.m8n8.x4.shared.b16 {%0,%1,%2,%3}, [%4];"
        : "=r"(r[0]), "=r"(r[1]), "=r"(r[2]), "=r"(r[3]) : "r"(a));
}
__device__ __forceinline__ void ldsm4t(uint32_t* r, uint32_t a) {
    asm volatile("ldmatrix.sync.aligned.m8n8.x4.trans.shared.b16 {%0,%1,%2,%3}, [%4];"
        : "=r"(r[0]), "=r"(r[1]), "=r"(r[2]), "=r"(r[3]) : "r"(a));
}
// fp32-accum HMMA
__device__ __forceinline__ void mma16816(float* d, const uint32_t* a,
                                         uint32_t b0, uint32_t b1) {
    asm volatile(
        "mma.sync.aligned.m16n8k16.row.col.f32.f16.f16.f32 "
        "{%0,%1,%2,%3}, {%4,%5,%6,%7}, {%8,%9}, {%0,%1,%2,%3};"
        : "+f"(d[0]), "+f"(d[1]), "+f"(d[2]), "+f"(d[3])
        : "r"(a[0]), "r"(a[1]), "r"(a[2]), "r"(a[3]), "r"(b0), "r"(b1));
}
// fp16-accum HMMA
__device__ __forceinline__ void mma16816f16(uint32_t* d, const uint32_t* a,
                                            uint32_t b0, uint32_t b1) {
    asm volatile(
        "mma.sync.aligned.m16n8k16.row.col.f16.f16.f16.f16 "
        "{%0,%1}, {%2,%3,%4,%5}, {%6,%7}, {%0,%1};"
        : "+r"(d[0]), "+r"(d[1])
        : "r"(a[0]), "r"(a[1]), "r"(a[2]), "r"(a[3]), "r"(b0), "r"(b1));
}
__device__ __forceinline__ uint32_t ex2h2(uint32_t v) {
    uint32_t r; asm("ex2.approx.f16x2 %0, %1;" : "=r"(r) : "r"(v)); return r;
}
__device__ __forceinline__ void sts32(uint32_t a, uint32_t v) {
    asm volatile("st.shared.b32 [%0], %1;" :: "r"(a), "r"(v) : "memory");
}
__device__ __forceinline__ void sts128(uint32_t a, uint32_t v0, uint32_t v1,
                                       uint32_t v2, uint32_t v3) {
    asm volatile("st.shared.v4.b32 [%0], {%1,%2,%3,%4};"
        :: "r"(a), "r"(v0), "r"(v1), "r"(v2), "r"(v3) : "memory");
}

// ---------------------------------------------------------------------------
// Projection via HMMA: O[16384,64] = fp16(A[16384,512]) @ fp16(W[512,64]).
// Q output pre-scaled by log2e. doF writes g_hh too.
// ---------------------------------------------------------------------------
__global__ __launch_bounds__(256) void proj_kernel(
    const float* __restrict__ x, const float* __restrict__ in_h,
    const float* __restrict__ f, const float* __restrict__ g)
{
    const bool doF = (blockIdx.z == 1);
    const float* A  = doF ? in_h : x;
    const float* Wm = doF ? f : g;
    __half* O       = doF ? g_kh : g_qh;
    const float scaleO = doF ? 1.0f : 1.4426950408889634f;

    __shared__ char psm[16384 + 8192];
    const uint32_t sa = smem_u32(psm);
    const uint32_t sw = sa + 16384;

    const int m0  = blockIdx.x * 128;
    const int tid = threadIdx.x;
    const int wid = tid >> 5, lane = tid & 31;
    const int l16 = lane & 15, lhi = lane & 16;
    const int w16 = wid * 16;

    float acc[8][4];
    #pragma unroll
    for (int i = 0; i < 8; i++)
        #pragma unroll
        for (int j = 0; j < 4; j++) acc[i][j] = 0.f;

    for (int k0 = 0; k0 < CDIM; k0 += 64) {
        #pragma unroll
        for (int i = 0; i < 4; i++) {
            int lin = tid + i * 256;
            int row = lin >> 3, c8 = lin & 7;
            const float4* ap = (const float4*)(A + (size_t)(m0 + row) * CDIM + k0 + c8 * 8);
            float4 v0 = ap[0], v1 = ap[1];
            __half2 h0 = __floats2half2_rn(v0.x, v0.y);
            __half2 h1 = __floats2half2_rn(v0.z, v0.w);
            __half2 h2 = __floats2half2_rn(v1.x, v1.y);
            __half2 h3 = __floats2half2_rn(v1.z, v1.w);
            sts128(sa + SWZ(row * 128 + c8 * 16),
                   *(uint32_t*)&h0, *(uint32_t*)&h1, *(uint32_t*)&h2, *(uint32_t*)&h3);
            if (doF) {
                uint4 pk = make_uint4(*(uint32_t*)&h0, *(uint32_t*)&h1,
                                      *(uint32_t*)&h2, *(uint32_t*)&h3);
                *(uint4*)(g_hh + (size_t)(m0 + row) * CDIM + k0 + c8 * 8) = pk;
            }
        }
        #pragma unroll
        for (int i = 0; i < 2; i++) {
            int lin = tid + i * 256;
            int kk = lin >> 3, n8 = lin & 7;
            const float4* wp = (const float4*)(Wm + (size_t)(k0 + kk) * DDIM + n8 * 8);
            float4 v0 = wp[0], v1 = wp[1];
            __half2 h0 = __floats2half2_rn(v0.x, v0.y);
            __half2 h1 = __floats2half2_rn(v0.z, v0.w);
            __half2 h2 = __floats2half2_rn(v1.x, v1.y);
            __half2 h3 = __floats2half2_rn(v1.z, v1.w);
            sts128(sw + SWZ(kk * 128 + n8 * 16),
                   *(uint32_t*)&h0, *(uint32_t*)&h1, *(uint32_t*)&h2, *(uint32_t*)&h3);
        }
        __syncthreads();

        #pragma unroll
        for (int ks = 0; ks < 4; ks++) {
            uint32_t a[4];
            ldsm4(a, sa + SWZ((w16 + l16) * 128 + ks * 32 + lhi));
            #pragma unroll
            for (int cb = 0; cb < 4; cb++) {
                uint32_t b[4];
                ldsm4t(b, sw + SWZ((ks * 16 + l16) * 128 + cb * 32 + lhi));
                mma16816(acc[2 * cb],     a, b[0], b[1]);
                mma16816(acc[2 * cb + 1], a, b[2], b[3]);
            }
        }
        __syncthreads();
    }

    const int r = w16 + (lane >> 2);
    const int cb2 = (lane & 3) * 2;
    #pragma unroll
    for (int nt = 0; nt < 8; nt++) {
        __half2 v0 = __floats2half2_rn(scaleO * acc[nt][0], scaleO * acc[nt][1]);
        __half2 v1 = __floats2half2_rn(scaleO * acc[nt][2], scaleO * acc[nt][3]);
        *(__half2*)(O + (size_t)(m0 + r) * DDIM + nt * 8 + cb2)     = v0;
        *(__half2*)(O + (size_t)(m0 + r + 8) * DDIM + nt * 8 + cb2) = v1;
    }
}

// ---------------------------------------------------------------------------
// Fused attention: R11 structure + paired-warp M=32 PV.
// 256 thr / 8 warps; CTA 128q x 256c; KT=64; 2-stage cp.async; 2 CTAs/SM.
// S: warp w -> rows 16w (no dup), fp16 accum, ex2, ones-denom; own P kept
//    in registers, ALSO parked to SMEM for the partner warp.
// PV: warp pair (2j,2j+1) -> 32q x 128c each warp (qw=w>>1, cw=w&1);
//     each H ldsm4t feeds 4 MMAs (own-A from regs, partner-A from SMEM).
// SMEM: Q 16K | K 2x8K | H 2x32K | P 16K = 114688 B (2x = 224K <= 227K)
// ---------------------------------------------------------------------------
#define SM_Q     0
#define SM_K     16384
#define SM_H     32768
#define SM_P     98304
#define SMEM_TOTAL 114688

__global__ __launch_bounds__(256, 2)
void attn_kernel(const float* __restrict__ x, const float* __restrict__ gamma,
                 float* __restrict__ out)
{
    extern __shared__ char smem[];
    const uint32_t sb = smem_u32(smem);
    const int tid = threadIdx.x;
    const int wid = tid >> 5, lane = tid & 31;
    const int l16 = lane & 15;
    const int lhi = lane & 16;
    const int q0s = wid * 16;            // S rows (own)
    const int cw  = wid & 1;             // PV channel half (0..1)
    const int qpair = (wid >> 1) * 32;   // PV rows base (shared by pair)
    const int ownSub = wid & 1 ? 1 : 0;  // own 16q position within pair:
                                         // even warp -> lower (sub 0), odd -> upper (sub 1)
    // NOTE: even warp (wid=2j) has q0s = 32j = qpair + 0; odd has qpair + 16.
    const int mySub  = (q0s - qpair) >> 4;   // 0 or 1 (== wid&1)
    const int nbSub  = 1 - mySub;

    const int qt = blockIdx.x, ch = blockIdx.y, b = blockIdx.z;
    const int qbase = qt * 128, chbase = ch * 256;
    const size_t boff = (size_t)b * NSEQ;

    // PV fp16 accumulators: [qsub 0..1][nblk 0..15 over 128c][rows r, r+8]
    uint32_t acc16[2][16][2];
    #pragma unroll
    for (int i = 0; i < 2; i++)
        #pragma unroll
        for (int j = 0; j < 16; j++) { acc16[i][j][0] = 0u; acc16[i][j][1] = 0u; }
    float dacc[4] = {0.f, 0.f, 0.f, 0.f};
    uint32_t qf[4][4];

    // staging coords
    const int srow = tid >> 3, sc8 = tid & 7;   // Q/K: 32 rows per pass
    const int hk = tid >> 5, hc = tid & 31;     // H: 8 rows per pass
    const int hpanel = hc >> 3, hpc8 = hc & 7;

    // ---- Prologue: Q + tile 0 ----
    #pragma unroll
    for (int i = 0; i < 4; i++) {
        int row = srow + i * 32;
        cp16(sb + SM_Q + SWZ(row * 128 + sc8 * 16),
             g_qh + (boff + qbase + row) * DDIM + sc8 * 8);
    }
    #pragma unroll
    for (int i = 0; i < 2; i++) {
        int row = srow + i * 32;
        cp16(sb + SM_K + SWZ(row * 128 + sc8 * 16),
             g_kh + (boff + row) * DDIM + sc8 * 8);
    }
    #pragma unroll
    for (int i = 0; i < 8; i++) {
        int k = hk + i * 8;
        cp16(sb + SM_H + hpanel * 8192 + SWZ(k * 128 + hpc8 * 16),
             g_hh + (boff + k) * CDIM + chbase + hc * 8);
    }
    CP_COMMIT();

    for (int t = 0; t < 64; t++) {
        CP_WAIT0();        // tile t resident
        __syncthreads();   // publish t; PV(t-1) done -> P free; buf (t+1)&1 free

        if (t < 63) {
            const int kt1 = (t + 1) * 64;
            const int s1 = (t + 1) & 1;
            const uint32_t kbuf = sb + SM_K + s1 * 8192;
            const uint32_t hbuf = sb + SM_H + s1 * 32768;
            #pragma unroll
            for (int i = 0; i < 2; i++) {
                int row = srow + i * 32;
                cp16(kbuf + SWZ(row * 128 + sc8 * 16),
                     g_kh + (boff + kt1 + row) * DDIM + sc8 * 8);
            }
            #pragma unroll
            for (int i = 0; i < 8; i++) {
                int k = hk + i * 8;
                cp16(hbuf + hpanel * 8192 + SWZ(k * 128 + hpc8 * 16),
                     g_hh + (boff + kt1 + k) * CDIM + chbase + hc * 8);
            }
            CP_COMMIT();
        }

        if (t == 0) {
            #pragma unroll
            for (int ks = 0; ks < 4; ks++)
                ldsm4(qf[ks], sb + SM_Q + SWZ((q0s + l16) * 128 + ks * 32 + lhi));
        }

        const int st = t & 1;
        const uint32_t kb = sb + SM_K + st * 8192;
        const uint32_t hb = sb + SM_H + st * 32768;

        // ---- S phase: rows q0s..q0s+15 x 64 keys, fp16 accum; keep + park ----
        uint32_t sacc2[2][8];
        #pragma unroll
        for (int h = 0; h < 2; h++) {
            #pragma unroll
            for (int j = 0; j < 8; j++) sacc2[h][j] = 0u;
            #pragma unroll
            for (int ks = 0; ks < 4; ks++) {
                uint32_t b0[4], b1[4];
                ldsm4(b0, kb + SWZ((h * 32 + l16) * 128 + ks * 32 + lhi));
                ldsm4(b1, kb + SWZ((h * 32 + 16 + l16) * 128 + ks * 32 + lhi));
                mma16816f16(&sacc2[h][0], qf[ks], b0[0], b0[2]);
                mma16816f16(&sacc2[h][2], qf[ks], b0[1], b0[3]);
                mma16816f16(&sacc2[h][4], qf[ks], b1[0], b1[2]);
                mma16816f16(&sacc2[h][6], qf[ks], b1[1], b1[3]);
            }
            #pragma unroll
            for (int j = 0; j < 8; j++) sacc2[h][j] = ex2h2(sacc2[h][j]);

            mma16816(dacc, &sacc2[h][0], ONES_H2, ONES_H2);
            mma16816(dacc, &sacc2[h][4], ONES_H2, ONES_H2);

            // park own P for the partner warp
            const int ra = q0s + (lane >> 2);
            #pragma unroll
            for (int j = 0; j < 4; j++) {
                const int colb = h * 64 + j * 16 + (lane & 3) * 4;
                sts32(sb + SM_P + SWZ(ra * 128 + colb),       sacc2[h][2 * j]);
                sts32(sb + SM_P + SWZ((ra + 8) * 128 + colb), sacc2[h][2 * j + 1]);
            }
        }
        __syncthreads();   // P published to partner

        // ---- PV phase: pair tile 32q x 128c; H fragment feeds 4 MMAs ----
        #pragma unroll
        for (int ksp = 0; ksp < 4; ksp++) {
            uint32_t nbrA[4];
            ldsm4(nbrA, sb + SM_P + SWZ((qpair + nbSub * 16 + l16) * 128 + ksp * 32 + lhi));
            const uint32_t* ownA = &sacc2[ksp >> 1][(ksp & 1) * 4];
            #pragma unroll
            for (int cb = 0; cb < 8; cb++) {
                const int panel = cw * 2 + (cb >> 2);
                const int colb = (cb & 3) * 32;
                uint32_t r[4];
                ldsm4t(r, hb + panel * 8192 + SWZ((ksp * 16 + l16) * 128 + colb + lhi));
                mma16816f16(acc16[mySub][2 * cb],     ownA, r[0], r[1]);
                mma16816f16(acc16[mySub][2 * cb + 1], ownA, r[2], r[3]);
                mma16816f16(acc16[nbSub][2 * cb],     nbrA, r[0], r[1]);
                mma16816f16(acc16[nbSub][2 * cb + 1], nbrA, r[2], r[3]);
            }
        }
    }

    // ---- denominators -> smem (reuse P region) ----
    __syncthreads();   // final PV reads of P done
    float* dinv = (float*)(smem + SM_P);
    if ((lane & 3) == 0) {
        dinv[q0s + (lane >> 2)]     = 1.0f / dacc[0];
        dinv[q0s + 8 + (lane >> 2)] = 1.0f / dacc[2];
    }
    __syncthreads();

    // ---- epilogue: out = gamma * o / denom + x ----
    const float gv = gamma[0];
    #pragma unroll
    for (int qsub = 0; qsub < 2; qsub++) {
        const int r0 = qpair + qsub * 16 + (lane >> 2);
        const float s0 = gv * dinv[r0];
        const float s1 = gv * dinv[r0 + 8];
        #pragma unroll
        for (int j = 0; j < 16; j++) {
            const int c = chbase + cw * 128 + (j >> 1) * 16 + (j & 1) * 8 + (lane & 3) * 2;
            size_t g0 = (boff + qbase + r0) * CDIM + c;
            size_t g1 = g0 + (size_t)8 * CDIM;
            float2 xv0 = *(const float2*)(x + g0);
            float2 xv1 = *(const float2*)(x + g1);
            float2 v0 = __half22float2(*(__half2*)&acc16[qsub][j][0]);
            float2 v1 = __half22float2(*(__half2*)&acc16[qsub][j][1]);
            float2 o0, o1;
            o0.x = s0 * v0.x + xv0.x;
            o0.y = s0 * v0.y + xv0.y;
            o1.x = s1 * v1.x + xv1.x;
            o1.y = s1 * v1.y + xv1.y;
            *(float2*)(out + g0) = o0;
            *(float2*)(out + g1) = o1;
        }
    }
}

// ---------------------------------------------------------------------------
extern "C" void kernel_launch(void* const* d_in, const int* in_sizes, int n_in,
                              void* d_out, int out_size)
{
    const float* x     = (const float*)d_in[0];
    const float* in_h  = (const float*)d_in[1];
    const float* f     = (const float*)d_in[2];
    const float* g     = (const float*)d_in[3];
    const float* gamma = (const float*)d_in[4];
    float* out = (float*)d_out;

    cudaFuncSetAttribute(attn_kernel, cudaFuncAttributeMaxDynamicSharedMemorySize, SMEM_TOTAL);

    proj_kernel<<<dim3((NB * NSEQ) / 128, 1, 2), 256>>>(x, in_h, f, g);
    attn_kernel<<<dim3(NSEQ / 128, 2, NB), 256, SMEM_TOTAL>>>(x, gamma, out);
}

// round 15
// speedup vs baseline: 3.4248x; 3.4248x over previous
#include <cuda_runtime.h>
#include <cuda_fp16.h>
#include <cstdint>

#define NB   4
#define NSEQ 4096
#define CDIM 512
#define DDIM 64

// fp16 scratch (allocation-free rule: __device__ globals)
__device__ __half g_qh[NB * NSEQ * DDIM];   // Q = (x @ g) * log2e
__device__ __half g_kh[NB * NSEQ * DDIM];   // K = input_h @ f
__device__ __half g_hh[NB * NSEQ * CDIM];   // input_h fp16

#define SWZ(x) ((x) ^ (((x) >> 3) & 0x70))
#define ONES_H2 0x3C003C00u

// ---------------------------------------------------------------------------
__device__ __forceinline__ uint32_t smem_u32(const void* p) {
    uint32_t a;
    asm("{ .reg .u64 t; cvta.to.shared.u64 t, %1; cvt.u32.u64 %0, t; }" : "=r"(a) : "l"(p));
    return a;
}
__device__ __forceinline__ void cp16(uint32_t s, const void* g) {
    asm volatile("cp.async.cg.shared.global [%0], [%1], 16;" :: "r"(s), "l"(g));
}
#define CP_COMMIT() asm volatile("cp.async.commit_group;" ::: "memory")
#define CP_WAIT0()  asm volatile("cp.async.wait_group 0;" ::: "memory")

__device__ __forceinline__ void ldsm4(uint32_t* r, uint32_t a) {
    asm volatile("ldmatrix.sync.aligned.m8n8.x4.shared.b16 {%0,%1,%2,%3}, [%4];"
        : "=r"(r[0]), "=r"(r[1]), "=r"(r[2]), "=r"(r[3]) : "r"(a));
}
__device__ __forceinline__ void ldsm4t(uint32_t* r, uint32_t a) {
    asm volatile("ldmatrix.sync.aligned.m8n8.x4.trans.shared.b16 {%0,%1,%2,%3}, [%4];"
        : "=r"(r[0]), "=r"(r[1]), "=r"(r[2]), "=r"(r[3]) : "r"(a));
}
// fp32-accum HMMA
__device__ __forceinline__ void mma16816(float* d, const uint32_t* a,
                                         uint32_t b0, uint32_t b1) {
    asm volatile(
        "mma.sync.aligned.m16n8k16.row.col.f32.f16.f16.f32 "
        "{%0,%1,%2,%3}, {%4,%5,%6,%7}, {%8,%9}, {%0,%1,%2,%3};"
        : "+f"(d[0]), "+f"(d[1]), "+f"(d[2]), "+f"(d[3])
        : "r"(a[0]), "r"(a[1]), "r"(a[2]), "r"(a[3]), "r"(b0), "r"(b1));
}
// fp16-accum HMMA
__device__ __forceinline__ void mma16816f16(uint32_t* d, const uint32_t* a,
                                            uint32_t b0, uint32_t b1) {
    asm volatile(
        "mma.sync.aligned.m16n8k16.row.col.f16.f16.f16.f16 "
        "{%0,%1}, {%2,%3,%4,%5}, {%6,%7}, {%0,%1};"
        : "+r"(d[0]), "+r"(d[1])
        : "r"(a[0]), "r"(a[1]), "r"(a[2]), "r"(a[3]), "r"(b0), "r"(b1));
}
__device__ __forceinline__ uint32_t ex2h2(uint32_t v) {
    uint32_t r; asm("ex2.approx.f16x2 %0, %1;" : "=r"(r) : "r"(v)); return r;
}
__device__ __forceinline__ void sts32(uint32_t a, uint32_t v) {
    asm volatile("st.shared.b32 [%0], %1;" :: "r"(a), "r"(v) : "memory");
}
__device__ __forceinline__ void sts128(uint32_t a, uint32_t v0, uint32_t v1,
                                       uint32_t v2, uint32_t v3) {
    asm volatile("st.shared.v4.b32 [%0], {%1,%2,%3,%4};"
        :: "r"(a), "r"(v0), "r"(v1), "r"(v2), "r"(v3) : "memory");
}

// ---------------------------------------------------------------------------
// Projection via HMMA: O[16384,64] = fp16(A[16384,512]) @ fp16(W[512,64]).
// Q output pre-scaled by log2e. doF writes g_hh too.
// ---------------------------------------------------------------------------
__global__ __launch_bounds__(256) void proj_kernel(
    const float* __restrict__ x, const float* __restrict__ in_h,
    const float* __restrict__ f, const float* __restrict__ g)
{
    const bool doF = (blockIdx.z == 1);
    const float* A  = doF ? in_h : x;
    const float* Wm = doF ? f : g;
    __half* O       = doF ? g_kh : g_qh;
    const float scaleO = doF ? 1.0f : 1.4426950408889634f;

    __shared__ char psm[16384 + 8192];
    const uint32_t sa = smem_u32(psm);
    const uint32_t sw = sa + 16384;

    const int m0  = blockIdx.x * 128;
    const int tid = threadIdx.x;
    const int wid = tid >> 5, lane = tid & 31;
    const int l16 = lane & 15, lhi = lane & 16;
    const int w16 = wid * 16;

    float acc[8][4];
    #pragma unroll
    for (int i = 0; i < 8; i++)
        #pragma unroll
        for (int j = 0; j < 4; j++) acc[i][j] = 0.f;

    for (int k0 = 0; k0 < CDIM; k0 += 64) {
        #pragma unroll
        for (int i = 0; i < 4; i++) {
            int lin = tid + i * 256;
            int row = lin >> 3, c8 = lin & 7;
            const float4* ap = (const float4*)(A + (size_t)(m0 + row) * CDIM + k0 + c8 * 8);
            float4 v0 = ap[0], v1 = ap[1];
            __half2 h0 = __floats2half2_rn(v0.x, v0.y);
            __half2 h1 = __floats2half2_rn(v0.z, v0.w);
            __half2 h2 = __floats2half2_rn(v1.x, v1.y);
            __half2 h3 = __floats2half2_rn(v1.z, v1.w);
            sts128(sa + SWZ(row * 128 + c8 * 16),
                   *(uint32_t*)&h0, *(uint32_t*)&h1, *(uint32_t*)&h2, *(uint32_t*)&h3);
            if (doF) {
                uint4 pk = make_uint4(*(uint32_t*)&h0, *(uint32_t*)&h1,
                                      *(uint32_t*)&h2, *(uint32_t*)&h3);
                *(uint4*)(g_hh + (size_t)(m0 + row) * CDIM + k0 + c8 * 8) = pk;
            }
        }
        #pragma unroll
        for (int i = 0; i < 2; i++) {
            int lin = tid + i * 256;
            int kk = lin >> 3, n8 = lin & 7;
            const float4* wp = (const float4*)(Wm + (size_t)(k0 + kk) * DDIM + n8 * 8);
            float4 v0 = wp[0], v1 = wp[1];
            __half2 h0 = __floats2half2_rn(v0.x, v0.y);
            __half2 h1 = __floats2half2_rn(v0.z, v0.w);
            __half2 h2 = __floats2half2_rn(v1.x, v1.y);
            __half2 h3 = __floats2half2_rn(v1.z, v1.w);
            sts128(sw + SWZ(kk * 128 + n8 * 16),
                   *(uint32_t*)&h0, *(uint32_t*)&h1, *(uint32_t*)&h2, *(uint32_t*)&h3);
        }
        __syncthreads();

        #pragma unroll
        for (int ks = 0; ks < 4; ks++) {
            uint32_t a[4];
            ldsm4(a, sa + SWZ((w16 + l16) * 128 + ks * 32 + lhi));
            #pragma unroll
            for (int cb = 0; cb < 4; cb++) {
                uint32_t b[4];
                ldsm4t(b, sw + SWZ((ks * 16 + l16) * 128 + cb * 32 + lhi));
                mma16816(acc[2 * cb],     a, b[0], b[1]);
                mma16816(acc[2 * cb + 1], a, b[2], b[3]);
            }
        }
        __syncthreads();
    }

    const int r = w16 + (lane >> 2);
    const int cb2 = (lane & 3) * 2;
    #pragma unroll
    for (int nt = 0; nt < 8; nt++) {
        __half2 v0 = __floats2half2_rn(scaleO * acc[nt][0], scaleO * acc[nt][1]);
        __half2 v1 = __floats2half2_rn(scaleO * acc[nt][2], scaleO * acc[nt][3]);
        *(__half2*)(O + (size_t)(m0 + r) * DDIM + nt * 8 + cb2)     = v0;
        *(__half2*)(O + (size_t)(m0 + r + 8) * DDIM + nt * 8 + cb2) = v1;
    }
}

// ---------------------------------------------------------------------------
// Fused attention: paired-warp M=32 PV, statically-indexed accumulators.
// 256 thr / 8 warps; CTA 128q x 256c; KT=64; 2-stage cp.async; 2 CTAs/SM.
// S: warp w -> rows 16w, fp16 accum, ex2, ones-denom; own P kept in regs,
//    also parked to SMEM for the partner warp.
// PV: warp pair (2j,2j+1): each warp does 32q x 128c -> accOwn (own rows,
//     A from regs) + accNbr (partner rows, A from SMEM); each H ldsm4t
//     feeds 4 MMAs. Runtime sub-tile index used ONLY in addresses.
// SMEM: Q 16K | K 2x8K | H 2x32K | P 16K = 114688 B (2x = 224K <= 227K)
// ---------------------------------------------------------------------------
#define SM_Q     0
#define SM_K     16384
#define SM_H     32768
#define SM_P     98304
#define SMEM_TOTAL 114688

__global__ __launch_bounds__(256, 2)
void attn_kernel(const float* __restrict__ x, const float* __restrict__ gamma,
                 float* __restrict__ out)
{
    extern __shared__ char smem[];
    const uint32_t sb = smem_u32(smem);
    const int tid = threadIdx.x;
    const int wid = tid >> 5, lane = tid & 31;
    const int l16 = lane & 15;
    const int lhi = lane & 16;
    const int q0s = wid * 16;            // own S rows
    const int cw  = wid & 1;             // PV channel half (0..1)
    const int qpair = (wid >> 1) * 32;   // pair row base
    const int qNbr = qpair + (16 - (q0s - qpair));  // partner sub-tile base

    const int qt = blockIdx.x, ch = blockIdx.y, b = blockIdx.z;
    const int qbase = qt * 128, chbase = ch * 256;
    const size_t boff = (size_t)b * NSEQ;

    // fp16 accumulators, statically indexed only
    uint32_t accOwn[16][2], accNbr[16][2];
    #pragma unroll
    for (int j = 0; j < 16; j++) {
        accOwn[j][0] = 0u; accOwn[j][1] = 0u;
        accNbr[j][0] = 0u; accNbr[j][1] = 0u;
    }
    float dacc[4] = {0.f, 0.f, 0.f, 0.f};
    uint32_t qf[4][4];

    // staging coords
    const int srow = tid >> 3, sc8 = tid & 7;   // Q/K: 32 rows per pass
    const int hk = tid >> 5, hc = tid & 31;     // H: 8 rows per pass
    const int hpanel = hc >> 3, hpc8 = hc & 7;

    // ---- Prologue: Q + tile 0 ----
    #pragma unroll
    for (int i = 0; i < 4; i++) {
        int row = srow + i * 32;
        cp16(sb + SM_Q + SWZ(row * 128 + sc8 * 16),
             g_qh + (boff + qbase + row) * DDIM + sc8 * 8);
    }
    #pragma unroll
    for (int i = 0; i < 2; i++) {
        int row = srow + i * 32;
        cp16(sb + SM_K + SWZ(row * 128 + sc8 * 16),
             g_kh + (boff + row) * DDIM + sc8 * 8);
    }
    #pragma unroll
    for (int i = 0; i < 8; i++) {
        int k = hk + i * 8;
        cp16(sb + SM_H + hpanel * 8192 + SWZ(k * 128 + hpc8 * 16),
             g_hh + (boff + k) * CDIM + chbase + hc * 8);
    }
    CP_COMMIT();

    for (int t = 0; t < 64; t++) {
        CP_WAIT0();        // tile t resident
        __syncthreads();   // publish t; PV(t-1) done -> P free; buf (t+1)&1 free

        if (t < 63) {
            const int kt1 = (t + 1) * 64;
            const int s1 = (t + 1) & 1;
            const uint32_t kbuf = sb + SM_K + s1 * 8192;
            const uint32_t hbuf = sb + SM_H + s1 * 32768;
            #pragma unroll
            for (int i = 0; i < 2; i++) {
                int row = srow + i * 32;
                cp16(kbuf + SWZ(row * 128 + sc8 * 16),
                     g_kh + (boff + kt1 + row) * DDIM + sc8 * 8);
            }
            #pragma unroll
            for (int i = 0; i < 8; i++) {
                int k = hk + i * 8;
                cp16(hbuf + hpanel * 8192 + SWZ(k * 128 + hpc8 * 16),
                     g_hh + (boff + kt1 + k) * CDIM + chbase + hc * 8);
            }
            CP_COMMIT();
        }

        if (t == 0) {
            #pragma unroll
            for (int ks = 0; ks < 4; ks++)
                ldsm4(qf[ks], sb + SM_Q + SWZ((q0s + l16) * 128 + ks * 32 + lhi));
        }

        const int st = t & 1;
        const uint32_t kb = sb + SM_K + st * 8192;
        const uint32_t hb = sb + SM_H + st * 32768;

        // ---- S phase: rows q0s..q0s+15 x 64 keys, fp16 accum; keep + park ----
        uint32_t sacc2[2][8];
        #pragma unroll
        for (int h = 0; h < 2; h++) {
            #pragma unroll
            for (int j = 0; j < 8; j++) sacc2[h][j] = 0u;
            #pragma unroll
            for (int ks = 0; ks < 4; ks++) {
                uint32_t b0[4], b1[4];
                ldsm4(b0, kb + SWZ((h * 32 + l16) * 128 + ks * 32 + lhi));
                ldsm4(b1, kb + SWZ((h * 32 + 16 + l16) * 128 + ks * 32 + lhi));
                mma16816f16(&sacc2[h][0], qf[ks], b0[0], b0[2]);
                mma16816f16(&sacc2[h][2], qf[ks], b0[1], b0[3]);
                mma16816f16(&sacc2[h][4], qf[ks], b1[0], b1[2]);
                mma16816f16(&sacc2[h][6], qf[ks], b1[1], b1[3]);
            }
            #pragma unroll
            for (int j = 0; j < 8; j++) sacc2[h][j] = ex2h2(sacc2[h][j]);

            mma16816(dacc, &sacc2[h][0], ONES_H2, ONES_H2);
            mma16816(dacc, &sacc2[h][4], ONES_H2, ONES_H2);

            // park own P for the partner warp
            const int ra = q0s + (lane >> 2);
            #pragma unroll
            for (int j = 0; j < 4; j++) {
                const int colb = h * 64 + j * 16 + (lane & 3) * 4;
                sts32(sb + SM_P + SWZ(ra * 128 + colb),       sacc2[h][2 * j]);
                sts32(sb + SM_P + SWZ((ra + 8) * 128 + colb), sacc2[h][2 * j + 1]);
            }
        }
        __syncthreads();   // P published to partner

        // ---- PV phase: pair tile 32q x 128c; each H fragment feeds 4 MMAs ----
        #pragma unroll
        for (int ksp = 0; ksp < 4; ksp++) {
            uint32_t nbrA[4];
            ldsm4(nbrA, sb + SM_P + SWZ((qNbr + l16) * 128 + ksp * 32 + lhi));
            const uint32_t* ownA = &sacc2[ksp >> 1][(ksp & 1) * 4];
            #pragma unroll
            for (int cb = 0; cb < 8; cb++) {
                const int panel = cw * 2 + (cb >> 2);
                const int colb = (cb & 3) * 32;
                uint32_t r[4];
                ldsm4t(r, hb + panel * 8192 + SWZ((ksp * 16 + l16) * 128 + colb + lhi));
                mma16816f16(accOwn[2 * cb],     ownA, r[0], r[1]);
                mma16816f16(accOwn[2 * cb + 1], ownA, r[2], r[3]);
                mma16816f16(accNbr[2 * cb],     nbrA, r[0], r[1]);
                mma16816f16(accNbr[2 * cb + 1], nbrA, r[2], r[3]);
            }
        }
    }

    // ---- denominators -> smem (reuse P region) ----
    __syncthreads();   // final PV reads of P done
    float* dinv = (float*)(smem + SM_P);
    if ((lane & 3) == 0) {
        dinv[q0s + (lane >> 2)]     = 1.0f / dacc[0];
        dinv[q0s + 8 + (lane >> 2)] = 1.0f / dacc[2];
    }
    __syncthreads();

    // ---- epilogue: out = gamma * o / denom + x ----
    const float gv = gamma[0];
    // own rows
    {
        const int r0 = q0s + (lane >> 2);
        const float s0 = gv * dinv[r0];
        const float s1 = gv * dinv[r0 + 8];
        #pragma unroll
        for (int j = 0; j < 16; j++) {
            const int c = chbase + cw * 128 + (j >> 1) * 16 + (j & 1) * 8 + (lane & 3) * 2;
            size_t g0 = (boff + qbase + r0) * CDIM + c;
            size_t g1 = g0 + (size_t)8 * CDIM;
            float2 xv0 = *(const float2*)(x + g0);
            float2 xv1 = *(const float2*)(x + g1);
            float2 v0 = __half22float2(*(__half2*)&accOwn[j][0]);
            float2 v1 = __half22float2(*(__half2*)&accOwn[j][1]);
            float2 o0, o1;
            o0.x = s0 * v0.x + xv0.x;
            o0.y = s0 * v0.y + xv0.y;
            o1.x = s1 * v1.x + xv1.x;
            o1.y = s1 * v1.y + xv1.y;
            *(float2*)(out + g0) = o0;
            *(float2*)(out + g1) = o1;
        }
    }
    // partner rows
    {
        const int r0 = qNbr + (lane >> 2);
        const float s0 = gv * dinv[r0];
        const float s1 = gv * dinv[r0 + 8];
        #pragma unroll
        for (int j = 0; j < 16; j++) {
            const int c = chbase + cw * 128 + (j >> 1) * 16 + (j & 1) * 8 + (lane & 3) * 2;
            size_t g0 = (boff + qbase + r0) * CDIM + c;
            size_t g1 = g0 + (size_t)8 * CDIM;
            float2 xv0 = *(const float2*)(x + g0);
            float2 xv1 = *(const float2*)(x + g1);
            float2 v0 = __half22float2(*(__half2*)&accNbr[j][0]);
            float2 v1 = __half22float2(*(__half2*)&accNbr[j][1]);
            float2 o0, o1;
            o0.x = s0 * v0.x + xv0.x;
            o0.y = s0 * v0.y + xv0.y;
            o1.x = s1 * v1.x + xv1.x;
            o1.y = s1 * v1.y + xv1.y;
            *(float2*)(out + g0) = o0;
            *(float2*)(out + g1) = o1;
        }
    }
}

// ---------------------------------------------------------------------------
extern "C" void kernel_launch(void* const* d_in, const int* in_sizes, int n_in,
                              void* d_out, int out_size)
{
    const float* x     = (const float*)d_in[0];
    const float* in_h  = (const float*)d_in[1];
    const float* f     = (const float*)d_in[2];
    const float* g     = (const float*)d_in[3];
    const float* gamma = (const float*)d_in[4];
    float* out = (float*)d_out;

    cudaFuncSetAttribute(attn_kernel, cudaFuncAttributeMaxDynamicSharedMemorySize, SMEM_TOTAL);

    proj_kernel<<<dim3((NB * NSEQ) / 128, 1, 2), 256>>>(x, in_h, f, g);
    attn_kernel<<<dim3(NSEQ / 128, 2, NB), 256, SMEM_TOTAL>>>(x, gamma, out);
}

// round 16
// speedup vs baseline: 3.8688x; 1.1297x over previous
#include <cuda_runtime.h>
#include <cuda_fp16.h>
#include <cstdint>

#define NB   4
#define NSEQ 4096
#define CDIM 512
#define DDIM 64

// fp16 scratch (allocation-free rule: __device__ globals)
__device__ __half g_qh[NB * NSEQ * DDIM];   // Q = (x @ g) * log2e
__device__ __half g_kh[NB * NSEQ * DDIM];   // K = input_h @ f
__device__ __half g_hh[NB * NSEQ * CDIM];   // input_h fp16

#define SWZ(x) ((x) ^ (((x) >> 3) & 0x70))
#define ONES_H2 0x3C003C00u

// ---------------------------------------------------------------------------
__device__ __forceinline__ uint32_t smem_u32(const void* p) {
    uint32_t a;
    asm("{ .reg .u64 t; cvta.to.shared.u64 t, %1; cvt.u32.u64 %0, t; }" : "=r"(a) : "l"(p));
    return a;
}
__device__ __forceinline__ void cp16(uint32_t s, const void* g) {
    asm volatile("cp.async.cg.shared.global [%0], [%1], 16;" :: "r"(s), "l"(g));
}
#define CP_COMMIT() asm volatile("cp.async.commit_group;" ::: "memory")
#define CP_WAIT0()  asm volatile("cp.async.wait_group 0;" ::: "memory")

__device__ __forceinline__ void ldsm4(uint32_t* r, uint32_t a) {
    asm volatile("ldmatrix.sync.aligned.m8n8.x4.shared.b16 {%0,%1,%2,%3}, [%4];"
        : "=r"(r[0]), "=r"(r[1]), "=r"(r[2]), "=r"(r[3]) : "r"(a));
}
__device__ __forceinline__ void ldsm4t(uint32_t* r, uint32_t a) {
    asm volatile("ldmatrix.sync.aligned.m8n8.x4.trans.shared.b16 {%0,%1,%2,%3}, [%4];"
        : "=r"(r[0]), "=r"(r[1]), "=r"(r[2]), "=r"(r[3]) : "r"(a));
}
// fp32-accum HMMA
__device__ __forceinline__ void mma16816(float* d, const uint32_t* a,
                                         uint32_t b0, uint32_t b1) {
    asm volatile(
        "mma.sync.aligned.m16n8k16.row.col.f32.f16.f16.f32 "
        "{%0,%1,%2,%3}, {%4,%5,%6,%7}, {%8,%9}, {%0,%1,%2,%3};"
        : "+f"(d[0]), "+f"(d[1]), "+f"(d[2]), "+f"(d[3])
        : "r"(a[0]), "r"(a[1]), "r"(a[2]), "r"(a[3]), "r"(b0), "r"(b1));
}
// fp16-accum HMMA
__device__ __forceinline__ void mma16816f16(uint32_t* d, const uint32_t* a,
                                            uint32_t b0, uint32_t b1) {
    asm volatile(
        "mma.sync.aligned.m16n8k16.row.col.f16.f16.f16.f16 "
        "{%0,%1}, {%2,%3,%4,%5}, {%6,%7}, {%0,%1};"
        : "+r"(d[0]), "+r"(d[1])
        : "r"(a[0]), "r"(a[1]), "r"(a[2]), "r"(a[3]), "r"(b0), "r"(b1));
}
__device__ __forceinline__ uint32_t ex2h2(uint32_t v) {
    uint32_t r; asm("ex2.approx.f16x2 %0, %1;" : "=r"(r) : "r"(v)); return r;
}
__device__ __forceinline__ void sts128(uint32_t a, uint32_t v0, uint32_t v1,
                                       uint32_t v2, uint32_t v3) {
    asm volatile("st.shared.v4.b32 [%0], {%1,%2,%3,%4};"
        :: "r"(a), "r"(v0), "r"(v1), "r"(v2), "r"(v3) : "memory");
}

// ---------------------------------------------------------------------------
// Projection via HMMA: O[16384,64] = fp16(A[16384,512]) @ fp16(W[512,64]).
// Q output pre-scaled by log2e. doF writes g_hh too.
// ---------------------------------------------------------------------------
__global__ __launch_bounds__(256) void proj_kernel(
    const float* __restrict__ x, const float* __restrict__ in_h,
    const float* __restrict__ f, const float* __restrict__ g)
{
    const bool doF = (blockIdx.z == 1);
    const float* A  = doF ? in_h : x;
    const float* Wm = doF ? f : g;
    __half* O       = doF ? g_kh : g_qh;
    const float scaleO = doF ? 1.0f : 1.4426950408889634f;

    __shared__ char psm[16384 + 8192];
    const uint32_t sa = smem_u32(psm);
    const uint32_t sw = sa + 16384;

    const int m0  = blockIdx.x * 128;
    const int tid = threadIdx.x;
    const int wid = tid >> 5, lane = tid & 31;
    const int l16 = lane & 15, lhi = lane & 16;
    const int w16 = wid * 16;

    float acc[8][4];
    #pragma unroll
    for (int i = 0; i < 8; i++)
        #pragma unroll
        for (int j = 0; j < 4; j++) acc[i][j] = 0.f;

    for (int k0 = 0; k0 < CDIM; k0 += 64) {
        #pragma unroll
        for (int i = 0; i < 4; i++) {
            int lin = tid + i * 256;
            int row = lin >> 3, c8 = lin & 7;
            const float4* ap = (const float4*)(A + (size_t)(m0 + row) * CDIM + k0 + c8 * 8);
            float4 v0 = ap[0], v1 = ap[1];
            __half2 h0 = __floats2half2_rn(v0.x, v0.y);
            __half2 h1 = __floats2half2_rn(v0.z, v0.w);
            __half2 h2 = __floats2half2_rn(v1.x, v1.y);
            __half2 h3 = __floats2half2_rn(v1.z, v1.w);
            sts128(sa + SWZ(row * 128 + c8 * 16),
                   *(uint32_t*)&h0, *(uint32_t*)&h1, *(uint32_t*)&h2, *(uint32_t*)&h3);
            if (doF) {
                uint4 pk = make_uint4(*(uint32_t*)&h0, *(uint32_t*)&h1,
                                      *(uint32_t*)&h2, *(uint32_t*)&h3);
                *(uint4*)(g_hh + (size_t)(m0 + row) * CDIM + k0 + c8 * 8) = pk;
            }
        }
        #pragma unroll
        for (int i = 0; i < 2; i++) {
            int lin = tid + i * 256;
            int kk = lin >> 3, n8 = lin & 7;
            const float4* wp = (const float4*)(Wm + (size_t)(k0 + kk) * DDIM + n8 * 8);
            float4 v0 = wp[0], v1 = wp[1];
            __half2 h0 = __floats2half2_rn(v0.x, v0.y);
            __half2 h1 = __floats2half2_rn(v0.z, v0.w);
            __half2 h2 = __floats2half2_rn(v1.x, v1.y);
            __half2 h3 = __floats2half2_rn(v1.z, v1.w);
            sts128(sw + SWZ(kk * 128 + n8 * 16),
                   *(uint32_t*)&h0, *(uint32_t*)&h1, *(uint32_t*)&h2, *(uint32_t*)&h3);
        }
        __syncthreads();

        #pragma unroll
        for (int ks = 0; ks < 4; ks++) {
            uint32_t a[4];
            ldsm4(a, sa + SWZ((w16 + l16) * 128 + ks * 32 + lhi));
            #pragma unroll
            for (int cb = 0; cb < 4; cb++) {
                uint32_t b[4];
                ldsm4t(b, sw + SWZ((ks * 16 + l16) * 128 + cb * 32 + lhi));
                mma16816(acc[2 * cb],     a, b[0], b[1]);
                mma16816(acc[2 * cb + 1], a, b[2], b[3]);
            }
        }
        __syncthreads();
    }

    const int r = w16 + (lane >> 2);
    const int cb2 = (lane & 3) * 2;
    #pragma unroll
    for (int nt = 0; nt < 8; nt++) {
        __half2 v0 = __floats2half2_rn(scaleO * acc[nt][0], scaleO * acc[nt][1]);
        __half2 v1 = __floats2half2_rn(scaleO * acc[nt][2], scaleO * acc[nt][3]);
        *(__half2*)(O + (size_t)(m0 + r) * DDIM + nt * 8 + cb2)     = v0;
        *(__half2*)(O + (size_t)(m0 + r + 8) * DDIM + nt * 8 + cb2) = v1;
    }
}

// ---------------------------------------------------------------------------
// Fused attention (R11 base, Q fragments reloaded per iter to free registers).
// 256 thr / 8 warps; warp tile 16q x 256c; CTA 128q x 256c; KT=64; 2-stage
// cp.async, ONE barrier per iter; 2 CTAs/SM; fp16 PV accum; per-warp
// ones-MMA denominators (no SMEM reduction).
// SMEM: Q 16K | K 2x8K | H 2x32K = 98304 B
// ---------------------------------------------------------------------------
#define SM_Q     0
#define SM_K     16384
#define SM_H     32768
#define SMEM_TOTAL 98304

__global__ __launch_bounds__(256, 2)
void attn_kernel(const float* __restrict__ x, const float* __restrict__ gamma,
                 float* __restrict__ out)
{
    extern __shared__ char smem[];
    const uint32_t sb = smem_u32(smem);
    const int tid = threadIdx.x;
    const int wid = tid >> 5, lane = tid & 31;
    const int l16 = lane & 15;
    const int lhi = lane & 16;
    const int q0  = wid * 16;

    const int qt = blockIdx.x, ch = blockIdx.y, b = blockIdx.z;
    const int qbase = qt * 128, chbase = ch * 256;
    const size_t boff = (size_t)b * NSEQ;

    // fp16 accumulators: 32 n8-blocks x {rows r, rows r+8}
    uint32_t acc16[32][2];
    #pragma unroll
    for (int j = 0; j < 32; j++) { acc16[j][0] = 0u; acc16[j][1] = 0u; }
    float dacc[4] = {0.f, 0.f, 0.f, 0.f};

    // staging coords
    const int srow = tid >> 3, sc8 = tid & 7;   // Q/K: 32 rows per step
    const int hk = tid >> 5, hc = tid & 31;     // H: 8 rows per step, 32 c8 chunks
    const int hpanel = hc >> 3, hpc8 = hc & 7;

    // ---- Prologue: Q + tile 0 (one group) ----
    #pragma unroll
    for (int i = 0; i < 4; i++) {
        int row = srow + i * 32;
        cp16(sb + SM_Q + SWZ(row * 128 + sc8 * 16),
             g_qh + (boff + qbase + row) * DDIM + sc8 * 8);
    }
    #pragma unroll
    for (int i = 0; i < 2; i++) {
        int row = srow + i * 32;
        cp16(sb + SM_K + SWZ(row * 128 + sc8 * 16),
             g_kh + (boff + row) * DDIM + sc8 * 8);
    }
    #pragma unroll
    for (int i = 0; i < 8; i++) {
        int k = hk + i * 8;
        cp16(sb + SM_H + hpanel * 8192 + SWZ(k * 128 + hpc8 * 16),
             g_hh + (boff + k) * CDIM + chbase + hc * 8);
    }
    CP_COMMIT();

    for (int t = 0; t < 64; t++) {
        CP_WAIT0();        // tile t resident
        __syncthreads();   // publish t; all warps done with t-1 (frees buf (t+1)&1)

        if (t < 63) {
            const int kt1 = (t + 1) * 64;
            const int s1 = (t + 1) & 1;
            const uint32_t kbuf = sb + SM_K + s1 * 8192;
            const uint32_t hbuf = sb + SM_H + s1 * 32768;
            #pragma unroll
            for (int i = 0; i < 2; i++) {
                int row = srow + i * 32;
                cp16(kbuf + SWZ(row * 128 + sc8 * 16),
                     g_kh + (boff + kt1 + row) * DDIM + sc8 * 8);
            }
            #pragma unroll
            for (int i = 0; i < 8; i++) {
                int k = hk + i * 8;
                cp16(hbuf + hpanel * 8192 + SWZ(k * 128 + hpc8 * 16),
                     g_hh + (boff + kt1 + k) * CDIM + chbase + hc * 8);
            }
            CP_COMMIT();
        }

        // Q fragments reloaded each iter (short live range -> register slack)
        uint32_t qa[4][4];
        #pragma unroll
        for (int ks = 0; ks < 4; ks++)
            ldsm4(qa[ks], sb + SM_Q + SWZ((q0 + l16) * 128 + ks * 32 + lhi));

        const int st = t & 1;
        const uint32_t kb = sb + SM_K + st * 8192;
        const uint32_t hb = sb + SM_H + st * 32768;

        #pragma unroll
        for (int h = 0; h < 2; h++) {
            // ---- S = Q @ K^T (16q x 32k), fp16 accum ----
            uint32_t sacc[8] = {0, 0, 0, 0, 0, 0, 0, 0};
            #pragma unroll
            for (int ks = 0; ks < 4; ks++) {
                uint32_t b0[4], b1[4];
                ldsm4(b0, kb + SWZ((h * 32 + l16) * 128 + ks * 32 + lhi));
                ldsm4(b1, kb + SWZ((h * 32 + 16 + l16) * 128 + ks * 32 + lhi));
                mma16816f16(&sacc[0], qa[ks], b0[0], b0[2]);
                mma16816f16(&sacc[2], qa[ks], b0[1], b0[3]);
                mma16816f16(&sacc[4], qa[ks], b1[0], b1[2]);
                mma16816f16(&sacc[6], qa[ks], b1[1], b1[3]);
            }

            // ---- P = 2^S in place ----
            #pragma unroll
            for (int j = 0; j < 8; j++) sacc[j] = ex2h2(sacc[j]);

            // ---- denominators: dacc += P @ ones (fp32) ----
            mma16816(dacc, &sacc[0], ONES_H2, ONES_H2);
            mma16816(dacc, &sacc[4], ONES_H2, ONES_H2);

            // ---- PV: O += P @ H (16q x 256c), fp16 accum ----
            #pragma unroll
            for (int kpl = 0; kpl < 2; kpl++) {
                const int kk = h * 32 + kpl * 16;
                const uint32_t* a = &sacc[kpl * 4];
                #pragma unroll
                for (int cb = 0; cb < 16; cb++) {
                    const int panel = cb >> 2;
                    const int colb = (cb & 3) * 32;
                    uint32_t r[4];
                    ldsm4t(r, hb + panel * 8192 + SWZ((kk + l16) * 128 + colb + lhi));
                    mma16816f16(acc16[2 * cb],     a, r[0], r[1]);
                    mma16816f16(acc16[2 * cb + 1], a, r[2], r[3]);
                }
            }
        }
    }

    // ---- epilogue: out = gamma * o / denom + x (denoms warp-local) ----
    const float gv = gamma[0];
    const int r0 = q0 + (lane >> 2);
    const float s0 = gv / dacc[0];
    const float s1 = gv / dacc[2];
    #pragma unroll
    for (int j = 0; j < 32; j++) {
        const int cb = j >> 1, s = j & 1;
        const int c = chbase + cb * 16 + s * 8 + (lane & 3) * 2;
        size_t g0 = (boff + qbase + r0) * CDIM + c;
        size_t g1 = g0 + (size_t)8 * CDIM;
        float2 xv0 = *(const float2*)(x + g0);
        float2 xv1 = *(const float2*)(x + g1);
        float2 v0 = __half22float2(*(__half2*)&acc16[j][0]);
        float2 v1 = __half22float2(*(__half2*)&acc16[j][1]);
        float2 o0, o1;
        o0.x = s0 * v0.x + xv0.x;
        o0.y = s0 * v0.y + xv0.y;
        o1.x = s1 * v1.x + xv1.x;
        o1.y = s1 * v1.y + xv1.y;
        *(float2*)(out + g0) = o0;
        *(float2*)(out + g1) = o1;
    }
}

// ---------------------------------------------------------------------------
extern "C" void kernel_launch(void* const* d_in, const int* in_sizes, int n_in,
                              void* d_out, int out_size)
{
    const float* x     = (const float*)d_in[0];
    const float* in_h  = (const float*)d_in[1];
    const float* f     = (const float*)d_in[2];
    const float* g     = (const float*)d_in[3];
    const float* gamma = (const float*)d_in[4];
    float* out = (float*)d_out;

    cudaFuncSetAttribute(attn_kernel, cudaFuncAttributeMaxDynamicSharedMemorySize, SMEM_TOTAL);

    proj_kernel<<<dim3((NB * NSEQ) / 128, 1, 2), 256>>>(x, in_h, f, g);
    attn_kernel<<<dim3(NSEQ / 128, 2, NB), 256, SMEM_TOTAL>>>(x, gamma, out);
}

// round 17
// speedup vs baseline: 3.9168x; 1.0124x over previous
#include <cuda_runtime.h>
#include <cuda_fp16.h>
#include <cstdint>

#define NB   4
#define NSEQ 4096
#define CDIM 512
#define DDIM 64

// fp16 scratch (allocation-free rule: __device__ globals)
__device__ __half g_qh[NB * NSEQ * DDIM];   // Q = (x @ g) * log2e
__device__ __half g_kh[NB * NSEQ * DDIM];   // K = input_h @ f
__device__ __half g_hh[NB * NSEQ * CDIM];   // input_h fp16

#define SWZ(x) ((x) ^ (((x) >> 3) & 0x70))
#define ONES_H2 0x3C003C00u

// ---------------------------------------------------------------------------
__device__ __forceinline__ uint32_t smem_u32(const void* p) {
    uint32_t a;
    asm("{ .reg .u64 t; cvta.to.shared.u64 t, %1; cvt.u32.u64 %0, t; }" : "=r"(a) : "l"(p));
    return a;
}
__device__ __forceinline__ void cp16(uint32_t s, const void* g) {
    asm volatile("cp.async.cg.shared.global [%0], [%1], 16;" :: "r"(s), "l"(g));
}
#define CP_COMMIT() asm volatile("cp.async.commit_group;" ::: "memory")
#define CP_WAIT0()  asm volatile("cp.async.wait_group 0;" ::: "memory")

__device__ __forceinline__ void ldsm4(uint32_t* r, uint32_t a) {
    asm volatile("ldmatrix.sync.aligned.m8n8.x4.shared.b16 {%0,%1,%2,%3}, [%4];"
        : "=r"(r[0]), "=r"(r[1]), "=r"(r[2]), "=r"(r[3]) : "r"(a));
}
__device__ __forceinline__ void ldsm4t(uint32_t* r, uint32_t a) {
    asm volatile("ldmatrix.sync.aligned.m8n8.x4.trans.shared.b16 {%0,%1,%2,%3}, [%4];"
        : "=r"(r[0]), "=r"(r[1]), "=r"(r[2]), "=r"(r[3]) : "r"(a));
}
// fp32-accum HMMA
__device__ __forceinline__ void mma16816(float* d, const uint32_t* a,
                                         uint32_t b0, uint32_t b1) {
    asm volatile(
        "mma.sync.aligned.m16n8k16.row.col.f32.f16.f16.f32 "
        "{%0,%1,%2,%3}, {%4,%5,%6,%7}, {%8,%9}, {%0,%1,%2,%3};"
        : "+f"(d[0]), "+f"(d[1]), "+f"(d[2]), "+f"(d[3])
        : "r"(a[0]), "r"(a[1]), "r"(a[2]), "r"(a[3]), "r"(b0), "r"(b1));
}
// fp16-accum HMMA
__device__ __forceinline__ void mma16816f16(uint32_t* d, const uint32_t* a,
                                            uint32_t b0, uint32_t b1) {
    asm volatile(
        "mma.sync.aligned.m16n8k16.row.col.f16.f16.f16.f16 "
        "{%0,%1}, {%2,%3,%4,%5}, {%6,%7}, {%0,%1};"
        : "+r"(d[0]), "+r"(d[1])
        : "r"(a[0]), "r"(a[1]), "r"(a[2]), "r"(a[3]), "r"(b0), "r"(b1));
}
__device__ __forceinline__ uint32_t ex2h2(uint32_t v) {
    uint32_t r; asm("ex2.approx.f16x2 %0, %1;" : "=r"(r) : "r"(v)); return r;
}
__device__ __forceinline__ void sts128(uint32_t a, uint32_t v0, uint32_t v1,
                                       uint32_t v2, uint32_t v3) {
    asm volatile("st.shared.v4.b32 [%0], {%1,%2,%3,%4};"
        :: "r"(a), "r"(v0), "r"(v1), "r"(v2), "r"(v3) : "memory");
}

// ---------------------------------------------------------------------------
// Projection via HMMA: O[16384,64] = fp16(A[16384,512]) @ fp16(W[512,64]).
// Q output pre-scaled by log2e. doF writes g_hh too.
// ---------------------------------------------------------------------------
__global__ __launch_bounds__(256) void proj_kernel(
    const float* __restrict__ x, const float* __restrict__ in_h,
    const float* __restrict__ f, const float* __restrict__ g)
{
    const bool doF = (blockIdx.z == 1);
    const float* A  = doF ? in_h : x;
    const float* Wm = doF ? f : g;
    __half* O       = doF ? g_kh : g_qh;
    const float scaleO = doF ? 1.0f : 1.4426950408889634f;

    __shared__ char psm[16384 + 8192];
    const uint32_t sa = smem_u32(psm);
    const uint32_t sw = sa + 16384;

    const int m0  = blockIdx.x * 128;
    const int tid = threadIdx.x;
    const int wid = tid >> 5, lane = tid & 31;
    const int l16 = lane & 15, lhi = lane & 16;
    const int w16 = wid * 16;

    float acc[8][4];
    #pragma unroll
    for (int i = 0; i < 8; i++)
        #pragma unroll
        for (int j = 0; j < 4; j++) acc[i][j] = 0.f;

    for (int k0 = 0; k0 < CDIM; k0 += 64) {
        #pragma unroll
        for (int i = 0; i < 4; i++) {
            int lin = tid + i * 256;
            int row = lin >> 3, c8 = lin & 7;
            const float4* ap = (const float4*)(A + (size_t)(m0 + row) * CDIM + k0 + c8 * 8);
            float4 v0 = ap[0], v1 = ap[1];
            __half2 h0 = __floats2half2_rn(v0.x, v0.y);
            __half2 h1 = __floats2half2_rn(v0.z, v0.w);
            __half2 h2 = __floats2half2_rn(v1.x, v1.y);
            __half2 h3 = __floats2half2_rn(v1.z, v1.w);
            sts128(sa + SWZ(row * 128 + c8 * 16),
                   *(uint32_t*)&h0, *(uint32_t*)&h1, *(uint32_t*)&h2, *(uint32_t*)&h3);
            if (doF) {
                uint4 pk = make_uint4(*(uint32_t*)&h0, *(uint32_t*)&h1,
                                      *(uint32_t*)&h2, *(uint32_t*)&h3);
                *(uint4*)(g_hh + (size_t)(m0 + row) * CDIM + k0 + c8 * 8) = pk;
            }
        }
        #pragma unroll
        for (int i = 0; i < 2; i++) {
            int lin = tid + i * 256;
            int kk = lin >> 3, n8 = lin & 7;
            const float4* wp = (const float4*)(Wm + (size_t)(k0 + kk) * DDIM + n8 * 8);
            float4 v0 = wp[0], v1 = wp[1];
            __half2 h0 = __floats2half2_rn(v0.x, v0.y);
            __half2 h1 = __floats2half2_rn(v0.z, v0.w);
            __half2 h2 = __floats2half2_rn(v1.x, v1.y);
            __half2 h3 = __floats2half2_rn(v1.z, v1.w);
            sts128(sw + SWZ(kk * 128 + n8 * 16),
                   *(uint32_t*)&h0, *(uint32_t*)&h1, *(uint32_t*)&h2, *(uint32_t*)&h3);
        }
        __syncthreads();

        #pragma unroll
        for (int ks = 0; ks < 4; ks++) {
            uint32_t a[4];
            ldsm4(a, sa + SWZ((w16 + l16) * 128 + ks * 32 + lhi));
            #pragma unroll
            for (int cb = 0; cb < 4; cb++) {
                uint32_t b[4];
                ldsm4t(b, sw + SWZ((ks * 16 + l16) * 128 + cb * 32 + lhi));
                mma16816(acc[2 * cb],     a, b[0], b[1]);
                mma16816(acc[2 * cb + 1], a, b[2], b[3]);
            }
        }
        __syncthreads();
    }

    const int r = w16 + (lane >> 2);
    const int cb2 = (lane & 3) * 2;
    #pragma unroll
    for (int nt = 0; nt < 8; nt++) {
        __half2 v0 = __floats2half2_rn(scaleO * acc[nt][0], scaleO * acc[nt][1]);
        __half2 v1 = __floats2half2_rn(scaleO * acc[nt][2], scaleO * acc[nt][3]);
        *(__half2*)(O + (size_t)(m0 + r) * DDIM + nt * 8 + cb2)     = v0;
        *(__half2*)(O + (size_t)(m0 + r + 8) * DDIM + nt * 8 + cb2) = v1;
    }
}

// ---------------------------------------------------------------------------
// Fused attention (R11 base, polished):
//  - Q fragments loaded gmem->regs ONCE (no Q SMEM at all)
//  - PV H-fragment loads software-pipelined (double-buffered ldsm4t)
// 256 thr / 8 warps; warp tile 16q x 256c; CTA 128q x 256c; KT=64; 2-stage
// cp.async, ONE barrier per iter; 2 CTAs/SM; fp16 PV accum; per-warp
// ones-MMA denominators.
// SMEM: K 2x8K | H 2x32K = 81920 B
// ---------------------------------------------------------------------------
#define SM_K     0
#define SM_H     16384
#define SMEM_TOTAL 81920

__global__ __launch_bounds__(256, 2)
void attn_kernel(const float* __restrict__ x, const float* __restrict__ gamma,
                 float* __restrict__ out)
{
    extern __shared__ char smem[];
    const uint32_t sb = smem_u32(smem);
    const int tid = threadIdx.x;
    const int wid = tid >> 5, lane = tid & 31;
    const int l16 = lane & 15;
    const int lhi = lane & 16;
    const int q0  = wid * 16;

    const int qt = blockIdx.x, ch = blockIdx.y, b = blockIdx.z;
    const int qbase = qt * 128, chbase = ch * 256;
    const size_t boff = (size_t)b * NSEQ;

    // fp16 accumulators: 32 n8-blocks x {rows r, rows r+8}
    uint32_t acc16[32][2];
    #pragma unroll
    for (int j = 0; j < 32; j++) { acc16[j][0] = 0u; acc16[j][1] = 0u; }
    float dacc[4] = {0.f, 0.f, 0.f, 0.f};

    // ---- Q fragments: gmem -> registers once (A-fragment layout) ----
    // a[ks] = { Q[r][ks16+c2], Q[r+8][ks16+c2], Q[r][ks16+8+c2], Q[r+8][ks16+8+c2] }
    uint32_t qf[4][4];
    {
        const int r = qbase + q0 + (lane >> 2);
        const int c2 = (lane & 3) * 2;
        const __half* q0p = g_qh + (boff + r) * DDIM;
        const __half* q1p = q0p + 8 * DDIM;
        #pragma unroll
        for (int ks = 0; ks < 4; ks++) {
            qf[ks][0] = *(const uint32_t*)(q0p + ks * 16 + c2);
            qf[ks][1] = *(const uint32_t*)(q1p + ks * 16 + c2);
            qf[ks][2] = *(const uint32_t*)(q0p + ks * 16 + 8 + c2);
            qf[ks][3] = *(const uint32_t*)(q1p + ks * 16 + 8 + c2);
        }
    }

    // staging coords
    const int srow = tid >> 3, sc8 = tid & 7;   // K: 32 rows per step
    const int hk = tid >> 5, hc = tid & 31;     // H: 8 rows per step, 32 c8 chunks
    const int hpanel = hc >> 3, hpc8 = hc & 7;

    // ---- Prologue: tile 0 ----
    #pragma unroll
    for (int i = 0; i < 2; i++) {
        int row = srow + i * 32;
        cp16(sb + SM_K + SWZ(row * 128 + sc8 * 16),
             g_kh + (boff + row) * DDIM + sc8 * 8);
    }
    #pragma unroll
    for (int i = 0; i < 8; i++) {
        int k = hk + i * 8;
        cp16(sb + SM_H + hpanel * 8192 + SWZ(k * 128 + hpc8 * 16),
             g_hh + (boff + k) * CDIM + chbase + hc * 8);
    }
    CP_COMMIT();

    for (int t = 0; t < 64; t++) {
        CP_WAIT0();        // tile t resident
        __syncthreads();   // publish t; all warps done with t-1 (frees buf (t+1)&1)

        if (t < 63) {
            const int kt1 = (t + 1) * 64;
            const int s1 = (t + 1) & 1;
            const uint32_t kbuf = sb + SM_K + s1 * 8192;
            const uint32_t hbuf = sb + SM_H + s1 * 32768;
            #pragma unroll
            for (int i = 0; i < 2; i++) {
                int row = srow + i * 32;
                cp16(kbuf + SWZ(row * 128 + sc8 * 16),
                     g_kh + (boff + kt1 + row) * DDIM + sc8 * 8);
            }
            #pragma unroll
            for (int i = 0; i < 8; i++) {
                int k = hk + i * 8;
                cp16(hbuf + hpanel * 8192 + SWZ(k * 128 + hpc8 * 16),
                     g_hh + (boff + kt1 + k) * CDIM + chbase + hc * 8);
            }
            CP_COMMIT();
        }

        const int st = t & 1;
        const uint32_t kb = sb + SM_K + st * 8192;
        const uint32_t hb = sb + SM_H + st * 32768;

        #pragma unroll
        for (int h = 0; h < 2; h++) {
            // ---- S = Q @ K^T (16q x 32k), fp16 accum ----
            uint32_t sacc[8] = {0, 0, 0, 0, 0, 0, 0, 0};
            #pragma unroll
            for (int ks = 0; ks < 4; ks++) {
                uint32_t b0[4], b1[4];
                ldsm4(b0, kb + SWZ((h * 32 + l16) * 128 + ks * 32 + lhi));
                ldsm4(b1, kb + SWZ((h * 32 + 16 + l16) * 128 + ks * 32 + lhi));
                mma16816f16(&sacc[0], qf[ks], b0[0], b0[2]);
                mma16816f16(&sacc[2], qf[ks], b0[1], b0[3]);
                mma16816f16(&sacc[4], qf[ks], b1[0], b1[2]);
                mma16816f16(&sacc[6], qf[ks], b1[1], b1[3]);
            }

            // ---- P = 2^S in place ----
            #pragma unroll
            for (int j = 0; j < 8; j++) sacc[j] = ex2h2(sacc[j]);

            // ---- denominators: dacc += P @ ones (fp32) ----
            mma16816(dacc, &sacc[0], ONES_H2, ONES_H2);
            mma16816(dacc, &sacc[4], ONES_H2, ONES_H2);

            // ---- PV: O += P @ H (16q x 256c), fp16 accum ----
            // H fragments double-buffered: next ldsm4t issues before MMAs
            #pragma unroll
            for (int kpl = 0; kpl < 2; kpl++) {
                const int kk = h * 32 + kpl * 16;
                const uint32_t* a = &sacc[kpl * 4];
                const uint32_t hrow = hb + SWZ((kk + l16) * 128 + lhi);
                uint32_t rr[2][4];
                ldsm4t(rr[0], hb + 0 * 8192 + SWZ((kk + l16) * 128 + 0 * 32 + lhi));
                #pragma unroll
                for (int cb = 0; cb < 16; cb++) {
                    if (cb < 15) {
                        const int nb2 = cb + 1;
                        ldsm4t(rr[(cb + 1) & 1],
                               hb + (nb2 >> 2) * 8192 +
                               SWZ((kk + l16) * 128 + (nb2 & 3) * 32 + lhi));
                    }
                    const uint32_t* r = rr[cb & 1];
                    mma16816f16(acc16[2 * cb],     a, r[0], r[1]);
                    mma16816f16(acc16[2 * cb + 1], a, r[2], r[3]);
                }
            }
        }
    }

    // ---- epilogue: out = gamma * o / denom + x (denoms warp-local) ----
    const float gv = gamma[0];
    const int r0 = q0 + (lane >> 2);
    const float s0 = gv / dacc[0];
    const float s1 = gv / dacc[2];
    #pragma unroll
    for (int j = 0; j < 32; j++) {
        const int cb = j >> 1, s = j & 1;
        const int c = chbase + cb * 16 + s * 8 + (lane & 3) * 2;
        size_t g0 = (boff + qbase + r0) * CDIM + c;
        size_t g1 = g0 + (size_t)8 * CDIM;
        float2 xv0 = *(const float2*)(x + g0);
        float2 xv1 = *(const float2*)(x + g1);
        float2 v0 = __half22float2(*(__half2*)&acc16[j][0]);
        float2 v1 = __half22float2(*(__half2*)&acc16[j][1]);
        float2 o0, o1;
        o0.x = s0 * v0.x + xv0.x;
        o0.y = s0 * v0.y + xv0.y;
        o1.x = s1 * v1.x + xv1.x;
        o1.y = s1 * v1.y + xv1.y;
        *(float2*)(out + g0) = o0;
        *(float2*)(out + g1) = o1;
    }
}

// ---------------------------------------------------------------------------
extern "C" void kernel_launch(void* const* d_in, const int* in_sizes, int n_in,
                              void* d_out, int out_size)
{
    const float* x     = (const float*)d_in[0];
    const float* in_h  = (const float*)d_in[1];
    const float* f     = (const float*)d_in[2];
    const float* g     = (const float*)d_in[3];
    const float* gamma = (const float*)d_in[4];
    float* out = (float*)d_out;

    cudaFuncSetAttribute(attn_kernel, cudaFuncAttributeMaxDynamicSharedMemorySize, SMEM_TOTAL);

    proj_kernel<<<dim3((NB * NSEQ) / 128, 1, 2), 256>>>(x, in_h, f, g);
    attn_kernel<<<dim3(NSEQ / 128, 2, NB), 256, SMEM_TOTAL>>>(x, gamma, out);
}